// round 5
// baseline (speedup 1.0000x reference)
#include <cuda_runtime.h>
#include <stdint.h>

#define N_NODES  50000
#define EDGE_CNT 1250000
#define TILE_E   32
#define NUM_TILES ((EDGE_CNT + TILE_E - 1) / TILE_E)

// transposed tile stride in floats (even -> 8B-aligned float2 rows)
#define STR 34

__device__ float g_counts[N_NODES];
__device__ int   g_idx_nonzero;   // >0 -> edge_index is int32

__device__ __forceinline__ float relu(float v) { return fmaxf(v, 0.0f); }

__global__ void zero_kernel(float* __restrict__ out) {
    int i = blockIdx.x * blockDim.x + threadIdx.x;
    int stride = gridDim.x * blockDim.x;
    if (i == 0) g_idx_nonzero = 0;
    for (int j = i; j < N_NODES * 64; j += stride) out[j] = 0.0f;
    for (int j = i; j < N_NODES; j += stride) g_counts[j] = 0.0f;
}

// If edge_index is int64 (values < 2^31), every odd int32 word is 0.
__global__ void detect_kernel(const int* __restrict__ eidx32) {
    int i = blockIdx.x * blockDim.x + threadIdx.x;
    int v = eidx32[2 * i + 1];
    if (v != 0) atomicOr(&g_idx_nonzero, 1);
}

__global__ void finalize_kernel(const float* __restrict__ x, float* __restrict__ out) {
    int i = blockIdx.x * blockDim.x + threadIdx.x;
    if (i < N_NODES * 64) {
        float c = g_counts[i >> 6];
        out[i] = x[i] + out[i] / fmaxf(c, 1.0f);
    }
}

__device__ __forceinline__ int load_edge(const void* eidx, int which, int e, bool is64) {
    long long v;
    if (is64) v = ((const long long*)eidx)[(long long)which * EDGE_CNT + e];
    else      v = ((const int*)eidx)[(long long)which * EDGE_CNT + e];
    int n = (int)v;
    return min(max(n, 0), N_NODES - 1);   // defensive clamp
}

__global__ void __launch_bounds__(256)
gnn_simt(const float* __restrict__ xfeat, const void* __restrict__ eidx,
         const float* __restrict__ ef,
         const float* __restrict__ W1, const float* __restrict__ b1,
         const float* __restrict__ W2, const float* __restrict__ b2,
         const float* __restrict__ W3, const float* __restrict__ b3,
         float* __restrict__ out) {
    __shared__ __align__(8) float sm_in[144 * STR];   // edge tile [144 K][32 E] (reused for h2)
    __shared__ __align__(8) float sm_h1[128 * STR];   // hidden1   [128 K][32 E]
    __shared__ int s_node[64];                        // [0..31]=src, [32..63]=tgt

    const int tid  = threadIdx.x;
    const int base = blockIdx.x * TILE_E;
    const bool is64 = (g_idx_nonzero == 0);

    // ---- edge indices ----
    if (tid < 64) {
        int e = base + (tid & 31);
        int v = 0;
        if (e < EDGE_CNT) v = load_edge(eidx, tid < 32 ? 0 : 1, e, is64);
        s_node[tid] = v;
    }
    __syncthreads();

    // ---- gather: [32 edges] x [144 feats] into transposed smem ----
    for (int F = tid; F < 32 * 36; F += 256) {
        int e = F / 36, f = F % 36;
        float4 v;
        if (f < 32) {
            int node = s_node[(f < 16 ? 0 : 32) + e];
            v = ((const float4*)(xfeat + (long long)node * 64))[f & 15];
        } else {
            int ge = base + e;
            if (ge < EDGE_CNT) v = ((const float4*)(ef + (long long)ge * 16))[f - 32];
            else               v = make_float4(0.f, 0.f, 0.f, 0.f);
        }
        int k = f * 4;
        sm_in[(k + 0) * STR + e] = v.x;
        sm_in[(k + 1) * STR + e] = v.y;
        sm_in[(k + 2) * STR + e] = v.z;
        sm_in[(k + 3) * STR + e] = v.w;
    }
    __syncthreads();

    // GEMM1/2 thread mapping: 64 col-pairs x 4 edge-groups(8 edges)
    const int colp = tid & 63;   // cols 2*colp, 2*colp+1
    const int eg   = tid >> 6;   // edges eg*8 .. eg*8+7
    const int c0   = colp * 2;

    // ---- GEMM1: h1 = relu(edge @ W1 + b1), K=144 ----
    {
        float a0[8] = {0,0,0,0,0,0,0,0};
        float a1[8] = {0,0,0,0,0,0,0,0};
#pragma unroll 2
        for (int k = 0; k < 144; k++) {
            float2 wv = ((const float2*)(W1 + k * 128))[colp];
            const float2* row = (const float2*)(sm_in + k * STR + eg * 8);
#pragma unroll
            for (int p = 0; p < 4; p++) {
                float2 a = row[p];
                a0[2*p]   = fmaf(a.x, wv.x, a0[2*p]);
                a0[2*p+1] = fmaf(a.y, wv.x, a0[2*p+1]);
                a1[2*p]   = fmaf(a.x, wv.y, a1[2*p]);
                a1[2*p+1] = fmaf(a.y, wv.y, a1[2*p+1]);
            }
        }
        float bb0 = b1[c0], bb1 = b1[c0 + 1];
        float2* H0 = (float2*)(sm_h1 + c0 * STR + eg * 8);
        float2* H1 = (float2*)(sm_h1 + (c0 + 1) * STR + eg * 8);
#pragma unroll
        for (int p = 0; p < 4; p++) {
            H0[p] = make_float2(relu(a0[2*p] + bb0), relu(a0[2*p+1] + bb0));
            H1[p] = make_float2(relu(a1[2*p] + bb1), relu(a1[2*p+1] + bb1));
        }
    }
    __syncthreads();

    // ---- GEMM2: h2 = relu(h1 @ W2 + b2), K=128; h2 overwrites sm_in ----
    {
        float a0[8] = {0,0,0,0,0,0,0,0};
        float a1[8] = {0,0,0,0,0,0,0,0};
#pragma unroll 2
        for (int k = 0; k < 128; k++) {
            float2 wv = ((const float2*)(W2 + k * 128))[colp];
            const float2* row = (const float2*)(sm_h1 + k * STR + eg * 8);
#pragma unroll
            for (int p = 0; p < 4; p++) {
                float2 a = row[p];
                a0[2*p]   = fmaf(a.x, wv.x, a0[2*p]);
                a0[2*p+1] = fmaf(a.y, wv.x, a0[2*p+1]);
                a1[2*p]   = fmaf(a.x, wv.y, a1[2*p]);
                a1[2*p+1] = fmaf(a.y, wv.y, a1[2*p+1]);
            }
        }
        float bb0 = b2[c0], bb1 = b2[c0 + 1];
        __syncthreads();   // order GEMM2's sm_in reads... (uniform; protects overwrite below)
        float2* H0 = (float2*)(sm_in + c0 * STR + eg * 8);
        float2* H1 = (float2*)(sm_in + (c0 + 1) * STR + eg * 8);
#pragma unroll
        for (int p = 0; p < 4; p++) {
            H0[p] = make_float2(relu(a0[2*p] + bb0), relu(a0[2*p+1] + bb0));
            H1[p] = make_float2(relu(a1[2*p] + bb1), relu(a1[2*p+1] + bb1));
        }
    }
    __syncthreads();

    // ---- GEMM3: msg = h2 @ W3 + b3 (N=64), scatter-add by target ----
    {
        const int colp3 = tid & 31;   // cols 2*colp3, 2*colp3+1
        const int eg3   = tid >> 5;   // edges eg3*4 .. eg3*4+3
        const int d0    = colp3 * 2;
        float a0[4] = {0,0,0,0};
        float a1[4] = {0,0,0,0};
#pragma unroll 2
        for (int k = 0; k < 128; k++) {
            float2 wv = ((const float2*)(W3 + k * 64))[colp3];
            const float2* row = (const float2*)(sm_in + k * STR + eg3 * 4);
#pragma unroll
            for (int p = 0; p < 2; p++) {
                float2 a = row[p];
                a0[2*p]   = fmaf(a.x, wv.x, a0[2*p]);
                a0[2*p+1] = fmaf(a.y, wv.x, a0[2*p+1]);
                a1[2*p]   = fmaf(a.x, wv.y, a1[2*p]);
                a1[2*p+1] = fmaf(a.y, wv.y, a1[2*p+1]);
            }
        }
        float bb0 = b3[d0], bb1 = b3[d0 + 1];
#pragma unroll
        for (int e = 0; e < 4; e++) {
            int edge = eg3 * 4 + e;
            if (base + edge < EDGE_CNT) {
                int tgt = s_node[32 + edge];
                float* dst = out + (long long)tgt * 64 + d0;
                asm volatile("red.global.add.v2.f32 [%0], {%1, %2};"
                             :: "l"(dst), "f"(a0[e] + bb0), "f"(a1[e] + bb1) : "memory");
            }
        }
        if (colp3 == 0) {
#pragma unroll
            for (int e = 0; e < 4; e++) {
                int edge = eg3 * 4 + e;
                if (base + edge < EDGE_CNT)
                    atomicAdd(&g_counts[s_node[32 + edge]], 1.0f);
            }
        }
    }
}

extern "C" void kernel_launch(void* const* d_in, const int* in_sizes, int n_in,
                              void* d_out, int out_size) {
    // identify inputs by element count (robust to ordering)
    const float *x = 0, *ef = 0, *W1 = 0, *W2 = 0, *W3 = 0, *b3 = 0;
    const float *b1 = 0, *b2 = 0;
    const void  *ei = 0;
    for (int i = 0; i < n_in; i++) {
        int s = in_sizes[i];
        if      (s == N_NODES * 64)  x  = (const float*)d_in[i];
        else if (s == 2 * EDGE_CNT)  ei = d_in[i];
        else if (s == EDGE_CNT * 16) ef = (const float*)d_in[i];
        else if (s == 144 * 128)     W1 = (const float*)d_in[i];
        else if (s == 128 * 128)     W2 = (const float*)d_in[i];
        else if (s == 128 * 64)      W3 = (const float*)d_in[i];
        else if (s == 64)            b3 = (const float*)d_in[i];
        else if (s == 128)           { if (!b1) b1 = (const float*)d_in[i]; else b2 = (const float*)d_in[i]; }
    }
    float* out = (float*)d_out;

    zero_kernel<<<2048, 256>>>(out);
    detect_kernel<<<16, 256>>>((const int*)ei);   // samples first 4096 odd words
    gnn_simt<<<NUM_TILES, 256>>>(x, ei, ef, W1, b1, W2, b2, W3, b3, out);
    finalize_kernel<<<(N_NODES * 64 + 255) / 256, 256>>>(x, out);
}

// round 11
// speedup vs baseline: 1.7995x; 1.7995x over previous
#include <cuda_runtime.h>
#include <cuda_bf16.h>
#include <stdint.h>

#define N_NODES  50000
#define EDGE_CNT 1250000
#define TILE_M   64
#define NUM_TILES ((EDGE_CNT + TILE_M - 1) / TILE_M)

#define K1 144
#define LD_A 168   // bf16 elems; 336B row stride (16B mult, conflict-free ldmatrix)
#define LD_H 136   // bf16 elems; 272B row stride

__device__ __align__(16) __nv_bfloat16 g_W1t[128 * K1];   // Wt[n][k]
__device__ __align__(16) __nv_bfloat16 g_W2t[128 * 128];
__device__ __align__(16) __nv_bfloat16 g_W3t[64 * 128];
__device__ float g_counts[N_NODES];
__device__ int   g_idx_nonzero;

__device__ __forceinline__ uint32_t pack_bf2(float lo, float hi) {
    uint32_t r;
    asm("cvt.rn.bf16x2.f32 %0, %1, %2;" : "=r"(r) : "f"(hi), "f"(lo));
    return r;
}
__device__ __forceinline__ int load_edge(const void* eidx, int which, int e, bool is64) {
    long long v;
    if (is64) v = ((const long long*)eidx)[(long long)which * EDGE_CNT + e];
    else      v = ((const int*)eidx)[(long long)which * EDGE_CNT + e];
    int n = (int)v;
    return min(max(n, 0), N_NODES - 1);
}

// ldmatrix x4: A-fragment for mma.m16n8k16 (rows16 strip, k-step base pointer)
__device__ __forceinline__ void lda_frag(uint32_t* a, const __nv_bfloat16* base, int ldm, int lane) {
    int mat = lane >> 3, r = lane & 7;
    const __nv_bfloat16* p = base + ((mat & 1) * 8 + r) * ldm + (mat >> 1) * 8;
    uint32_t addr = (uint32_t)__cvta_generic_to_shared(p);
    asm volatile("ldmatrix.sync.aligned.m8n8.x4.shared.b16 {%0,%1,%2,%3}, [%4];"
                 : "=r"(a[0]), "=r"(a[1]), "=r"(a[2]), "=r"(a[3]) : "r"(addr));
}
__device__ __forceinline__ void mma_bf16(float* c, const uint32_t* a, uint32_t b0, uint32_t b1) {
    asm volatile("mma.sync.aligned.m16n8k16.row.col.f32.bf16.bf16.f32 "
                 "{%0,%1,%2,%3}, {%4,%5,%6,%7}, {%8,%9}, {%0,%1,%2,%3};"
                 : "+f"(c[0]), "+f"(c[1]), "+f"(c[2]), "+f"(c[3])
                 : "r"(a[0]), "r"(a[1]), "r"(a[2]), "r"(a[3]), "r"(b0), "r"(b1));
}

__global__ void zero_kernel(float* __restrict__ out) {
    int i = blockIdx.x * blockDim.x + threadIdx.x;
    int stride = gridDim.x * blockDim.x;
    if (i == 0) g_idx_nonzero = 0;
    for (int j = i; j < N_NODES * 64; j += stride) out[j] = 0.0f;
    for (int j = i; j < N_NODES; j += stride) g_counts[j] = 0.0f;
}
__global__ void detect_kernel(const int* __restrict__ eidx32) {
    int i = blockIdx.x * blockDim.x + threadIdx.x;
    if (eidx32[2 * i + 1] != 0) atomicOr(&g_idx_nonzero, 1);
}
__global__ void wconv_kernel(const float* __restrict__ W1, const float* __restrict__ W2,
                             const float* __restrict__ W3) {
    int i = blockIdx.x * blockDim.x + threadIdx.x;
    if (i < 18432) {                        // W1 [144][128] -> Wt[n][k]
        int k = i >> 7, n = i & 127;
        g_W1t[n * K1 + k] = __float2bfloat16(W1[i]);
    } else if (i < 18432 + 16384) {         // W2 [128][128]
        int j = i - 18432;
        int k = j >> 7, n = j & 127;
        g_W2t[n * 128 + k] = __float2bfloat16(W2[j]);
    } else if (i < 43008) {                 // W3 [128][64]
        int j = i - 34816;
        int k = j >> 6, n = j & 63;
        g_W3t[n * 128 + k] = __float2bfloat16(W3[j]);
    }
}
__global__ void finalize_kernel(const float* __restrict__ x, float* __restrict__ out) {
    int i = blockIdx.x * blockDim.x + threadIdx.x;
    if (i < N_NODES * 64) {
        float c = g_counts[i >> 6];
        out[i] = x[i] + out[i] / fmaxf(c, 1.0f);
    }
}

__global__ void __launch_bounds__(256)
gnn_mma(const void* __restrict__ eidx, const float* __restrict__ ef,
        const float* __restrict__ xfeat,
        const float* __restrict__ b1, const float* __restrict__ b2,
        const float* __restrict__ b3, float* __restrict__ out) {
    __shared__ __align__(16) __nv_bfloat16 s_A[TILE_M * LD_A];  // 21504 B (A1 / h2)
    __shared__ __align__(16) __nv_bfloat16 s_H[TILE_M * LD_H];  // 17408 B (h1)
    __shared__ float s_b[320];
    __shared__ int   s_tgt[TILE_M];

    const int tid = threadIdx.x;
    const int w = tid >> 5, lane = tid & 31;
    const int strip = w & 3, colh = w >> 2;       // 4 row-strips x 2 col-halves
    const int rows16 = strip * 16;
    const int g = lane >> 2, tc = lane & 3;       // mma groupID / thread-in-group
    const bool is64 = (g_idx_nonzero == 0);
    const int base = blockIdx.x * TILE_M;

    // ---- bias + gather (64 edges x [64 src | 64 tgt | 16 ef]) ----
    if (tid < 128) { s_b[tid] = b1[tid]; s_b[128 + tid] = b2[tid]; }
    if (tid < 64)  s_b[256 + tid] = b3[tid];
    if (tid < 128) {
        int m = tid >> 1, half = tid & 1;
        int e = base + m;
        bool valid = e < EDGE_CNT;
        int node = valid ? load_edge(eidx, half, e, is64) : 0;
        if (half) s_tgt[m] = node;
        const float4* xr = (const float4*)(xfeat + (long long)node * 64);
        uint2* dst = (uint2*)(s_A + m * LD_A + half * 64);
#pragma unroll
        for (int i = 0; i < 16; i++) {
            float4 v = valid ? xr[i] : make_float4(0.f, 0.f, 0.f, 0.f);
            dst[i] = make_uint2(pack_bf2(v.x, v.y), pack_bf2(v.z, v.w));
        }
    } else if (tid < 192) {
        int m = tid - 128;
        int e = base + m;
        bool valid = e < EDGE_CNT;
        const float4* er = (const float4*)(ef + (long long)e * 16);
        uint2* dst = (uint2*)(s_A + m * LD_A + 128);
#pragma unroll
        for (int i = 0; i < 4; i++) {
            float4 v = valid ? er[i] : make_float4(0.f, 0.f, 0.f, 0.f);
            dst[i] = make_uint2(pack_bf2(v.x, v.y), pack_bf2(v.z, v.w));
        }
    }
    __syncthreads();

    // ---- GEMM1: h1 = relu(A[64x144] @ W1 + b1); warp: 16 rows x 64 cols ----
    {
        float c[8][4] = {};
#pragma unroll
        for (int k = 0; k < 9; k++) {
            uint32_t a[4];
            lda_frag(a, s_A + rows16 * LD_A + k * 16, LD_A, lane);
#pragma unroll
            for (int j = 0; j < 8; j++) {
                const __nv_bfloat16* wp = g_W1t + (colh * 64 + j * 8 + g) * K1 + k * 16 + tc * 2;
                uint32_t b0 = *(const uint32_t*)wp;
                uint32_t b1v = *(const uint32_t*)(wp + 8);
                mma_bf16(c[j], a, b0, b1v);
            }
        }
#pragma unroll
        for (int j = 0; j < 8; j++) {
            int col = colh * 64 + j * 8 + tc * 2;
            float bb0 = s_b[col], bb1 = s_b[col + 1];
            *(uint32_t*)(s_H + (rows16 + g) * LD_H + col) =
                pack_bf2(fmaxf(c[j][0] + bb0, 0.f), fmaxf(c[j][1] + bb1, 0.f));
            *(uint32_t*)(s_H + (rows16 + 8 + g) * LD_H + col) =
                pack_bf2(fmaxf(c[j][2] + bb0, 0.f), fmaxf(c[j][3] + bb1, 0.f));
        }
    }
    __syncthreads();

    // ---- GEMM2: h2 = relu(h1[64x128] @ W2 + b2) -> s_A ----
    {
        float c[8][4] = {};
#pragma unroll
        for (int k = 0; k < 8; k++) {
            uint32_t a[4];
            lda_frag(a, s_H + rows16 * LD_H + k * 16, LD_H, lane);
#pragma unroll
            for (int j = 0; j < 8; j++) {
                const __nv_bfloat16* wp = g_W2t + (colh * 64 + j * 8 + g) * 128 + k * 16 + tc * 2;
                uint32_t b0 = *(const uint32_t*)wp;
                uint32_t b1v = *(const uint32_t*)(wp + 8);
                mma_bf16(c[j], a, b0, b1v);
            }
        }
#pragma unroll
        for (int j = 0; j < 8; j++) {
            int col = colh * 64 + j * 8 + tc * 2;
            float bb0 = s_b[128 + col], bb1 = s_b[128 + col + 1];
            *(uint32_t*)(s_A + (rows16 + g) * LD_A + col) =
                pack_bf2(fmaxf(c[j][0] + bb0, 0.f), fmaxf(c[j][1] + bb1, 0.f));
            *(uint32_t*)(s_A + (rows16 + 8 + g) * LD_A + col) =
                pack_bf2(fmaxf(c[j][2] + bb0, 0.f), fmaxf(c[j][3] + bb1, 0.f));
        }
    }
    __syncthreads();

    // ---- GEMM3: msg = h2[64x128] @ W3[128x64] + b3; register scatter ----
    {
        float c[4][4] = {};
#pragma unroll
        for (int k = 0; k < 8; k++) {
            uint32_t a[4];
            lda_frag(a, s_A + rows16 * LD_A + k * 16, LD_A, lane);
#pragma unroll
            for (int j = 0; j < 4; j++) {
                const __nv_bfloat16* wp = g_W3t + (colh * 32 + j * 8 + g) * 128 + k * 16 + tc * 2;
                uint32_t b0 = *(const uint32_t*)wp;
                uint32_t b1v = *(const uint32_t*)(wp + 8);
                mma_bf16(c[j], a, b0, b1v);
            }
        }
        int r0 = rows16 + g, r1 = rows16 + 8 + g;
        bool v0 = (base + r0) < EDGE_CNT, v1 = (base + r1) < EDGE_CNT;
        int t0 = v0 ? s_tgt[r0] : 0, t1 = v1 ? s_tgt[r1] : 0;
#pragma unroll
        for (int j = 0; j < 4; j++) {
            int cj = colh * 32 + j * 8 + tc * 2;
            float bb0 = s_b[256 + cj], bb1 = s_b[256 + cj + 1];
            if (v0) {
                asm volatile("red.global.add.v2.f32 [%0], {%1, %2};"
                             :: "l"(out + (long long)t0 * 64 + cj),
                                "f"(c[j][0] + bb0), "f"(c[j][1] + bb1) : "memory");
            }
            if (v1) {
                asm volatile("red.global.add.v2.f32 [%0], {%1, %2};"
                             :: "l"(out + (long long)t1 * 64 + cj),
                                "f"(c[j][2] + bb0), "f"(c[j][3] + bb1) : "memory");
            }
        }
        if (colh == 0 && tc == 0) {
            if (v0) atomicAdd(&g_counts[t0], 1.0f);
            if (v1) atomicAdd(&g_counts[t1], 1.0f);
        }
    }
}

extern "C" void kernel_launch(void* const* d_in, const int* in_sizes, int n_in,
                              void* d_out, int out_size) {
    const float *x = 0, *ef = 0, *W1 = 0, *W2 = 0, *W3 = 0, *b3 = 0;
    const float *b1 = 0, *b2 = 0;
    const void  *ei = 0;
    for (int i = 0; i < n_in; i++) {
        int s = in_sizes[i];
        if      (s == N_NODES * 64)  x  = (const float*)d_in[i];
        else if (s == 2 * EDGE_CNT)  ei = d_in[i];
        else if (s == EDGE_CNT * 16) ef = (const float*)d_in[i];
        else if (s == 144 * 128)     W1 = (const float*)d_in[i];
        else if (s == 128 * 128)     W2 = (const float*)d_in[i];
        else if (s == 128 * 64)      W3 = (const float*)d_in[i];
        else if (s == 64)            b3 = (const float*)d_in[i];
        else if (s == 128)           { if (!b1) b1 = (const float*)d_in[i]; else b2 = (const float*)d_in[i]; }
    }
    float* out = (float*)d_out;

    zero_kernel<<<2048, 256>>>(out);
    detect_kernel<<<16, 256>>>((const int*)ei);
    wconv_kernel<<<(43008 + 255) / 256, 256>>>(W1, W2, W3);
    gnn_mma<<<NUM_TILES, 256>>>(ei, ef, x, b1, b2, b3, out);
    finalize_kernel<<<(N_NODES * 64 + 255) / 256, 256>>>(x, out);
}

// round 12
// speedup vs baseline: 4.9178x; 2.7329x over previous
#include <cuda_runtime.h>
#include <cuda_bf16.h>
#include <stdint.h>

#define N_NODES  50000
#define EDGE_CNT 1250000
#define TILE_M   64
#define NUM_TILES ((EDGE_CNT + TILE_M - 1) / TILE_M)

#define K1 144
#define LD_A 168   // bf16 elems; 336B row stride (conflict-free ldmatrix)
#define LD_H 136   // bf16 elems; 272B row stride

// fragment-packed weights: slot (kstep, ntile, lane) -> uint2 {b0, b1}
__device__ __align__(16) uint2 g_P1[9 * 16 * 32];   // 36864 B
__device__ __align__(16) uint2 g_P2[8 * 16 * 32];   // 32768 B
__device__ __align__(16) uint2 g_P3[8 *  8 * 32];   // 16384 B
__device__ float g_counts[N_NODES];
__device__ int   g_idx_nonzero;

__device__ __forceinline__ uint32_t pack_bf2(float lo, float hi) {
    uint32_t r;
    asm("cvt.rn.bf16x2.f32 %0, %1, %2;" : "=r"(r) : "f"(hi), "f"(lo));
    return r;
}
__device__ __forceinline__ int load_edge(const void* eidx, int which, int e, bool is64) {
    long long v;
    if (is64) v = ((const long long*)eidx)[(long long)which * EDGE_CNT + e];
    else      v = ((const int*)eidx)[(long long)which * EDGE_CNT + e];
    int n = (int)v;
    return min(max(n, 0), N_NODES - 1);
}

__device__ __forceinline__ void lda_frag(uint32_t* a, const __nv_bfloat16* base, int ldm, int lane) {
    int mat = lane >> 3, r = lane & 7;
    const __nv_bfloat16* p = base + ((mat & 1) * 8 + r) * ldm + (mat >> 1) * 8;
    uint32_t addr = (uint32_t)__cvta_generic_to_shared(p);
    asm volatile("ldmatrix.sync.aligned.m8n8.x4.shared.b16 {%0,%1,%2,%3}, [%4];"
                 : "=r"(a[0]), "=r"(a[1]), "=r"(a[2]), "=r"(a[3]) : "r"(addr));
}
__device__ __forceinline__ void mma_bf16(float* c, const uint32_t* a, uint32_t b0, uint32_t b1) {
    asm volatile("mma.sync.aligned.m16n8k16.row.col.f32.bf16.bf16.f32 "
                 "{%0,%1,%2,%3}, {%4,%5,%6,%7}, {%8,%9}, {%0,%1,%2,%3};"
                 : "+f"(c[0]), "+f"(c[1]), "+f"(c[2]), "+f"(c[3])
                 : "r"(a[0]), "r"(a[1]), "r"(a[2]), "r"(a[3]), "r"(b0), "r"(b1));
}

__global__ void zero_kernel(float* __restrict__ out) {
    int i = blockIdx.x * blockDim.x + threadIdx.x;
    int stride = gridDim.x * blockDim.x;
    if (i == 0) g_idx_nonzero = 0;
    for (int j = i; j < N_NODES * 64; j += stride) out[j] = 0.0f;
    for (int j = i; j < N_NODES; j += stride) g_counts[j] = 0.0f;
}
__global__ void detect_kernel(const int* __restrict__ eidx32) {
    int i = blockIdx.x * blockDim.x + threadIdx.x;
    if (eidx32[2 * i + 1] != 0) atomicOr(&g_idx_nonzero, 1);
}

// pack W (row-major [K][N]) into per-lane mma B-fragments
__global__ void wpack_kernel(const float* __restrict__ W1, const float* __restrict__ W2,
                             const float* __restrict__ W3) {
    int s = blockIdx.x * blockDim.x + threadIdx.x;
    if (s < 4608) {                               // GEMM1: 9 ksteps x 16 ntiles
        int K = s / 512, rem = s % 512, J = rem >> 5, lane = rem & 31;
        int g = lane >> 2, tc = lane & 3;
        int n = J * 8 + g, k0 = K * 16 + tc * 2;
        g_P1[s] = make_uint2(
            pack_bf2(W1[k0 * 128 + n],       W1[(k0 + 1) * 128 + n]),
            pack_bf2(W1[(k0 + 8) * 128 + n], W1[(k0 + 9) * 128 + n]));
    } else if (s < 4608 + 4096) {                 // GEMM2: 8 x 16
        int j = s - 4608;
        int K = j / 512, rem = j % 512, J = rem >> 5, lane = rem & 31;
        int g = lane >> 2, tc = lane & 3;
        int n = J * 8 + g, k0 = K * 16 + tc * 2;
        g_P2[j] = make_uint2(
            pack_bf2(W2[k0 * 128 + n],       W2[(k0 + 1) * 128 + n]),
            pack_bf2(W2[(k0 + 8) * 128 + n], W2[(k0 + 9) * 128 + n]));
    } else if (s < 4608 + 4096 + 2048) {          // GEMM3: 8 x 8
        int j = s - 8704;
        int K = j / 256, rem = j % 256, J = rem >> 5, lane = rem & 31;
        int g = lane >> 2, tc = lane & 3;
        int n = J * 8 + g, k0 = K * 16 + tc * 2;
        g_P3[j] = make_uint2(
            pack_bf2(W3[k0 * 64 + n],       W3[(k0 + 1) * 64 + n]),
            pack_bf2(W3[(k0 + 8) * 64 + n], W3[(k0 + 9) * 64 + n]));
    }
}
__global__ void finalize_kernel(const float* __restrict__ x, float* __restrict__ out) {
    int i = blockIdx.x * blockDim.x + threadIdx.x;
    if (i < N_NODES * 64) {
        float c = g_counts[i >> 6];
        out[i] = x[i] + out[i] / fmaxf(c, 1.0f);
    }
}

__global__ void __launch_bounds__(256)
gnn_mma(const void* __restrict__ eidx, const float* __restrict__ ef,
        const float* __restrict__ xfeat,
        const float* __restrict__ b1, const float* __restrict__ b2,
        const float* __restrict__ b3, float* __restrict__ out) {
    __shared__ __align__(16) __nv_bfloat16 s_A[TILE_M * LD_A];  // A1 / h2
    __shared__ __align__(16) __nv_bfloat16 s_H[TILE_M * LD_H];  // h1
    __shared__ float s_b[320];
    __shared__ int   s_tgt[TILE_M];

    const int tid = threadIdx.x;
    const int w = tid >> 5, lane = tid & 31;
    const int strip = w & 3, colh = w >> 2;       // 4 row-strips x 2 col-halves
    const int rows16 = strip * 16;
    const int g = lane >> 2, tc = lane & 3;
    const bool is64 = (g_idx_nonzero == 0);
    const int base = blockIdx.x * TILE_M;

    // ---- bias + gather ----
    if (tid < 128) { s_b[tid] = b1[tid]; s_b[128 + tid] = b2[tid]; }
    if (tid < 64)  s_b[256 + tid] = b3[tid];
    if (tid < 128) {
        int m = tid >> 1, half = tid & 1;
        int e = base + m;
        bool valid = e < EDGE_CNT;
        int node = valid ? load_edge(eidx, half, e, is64) : 0;
        if (half) s_tgt[m] = node;
        const float4* xr = (const float4*)(xfeat + (long long)node * 64);
        uint2* dst = (uint2*)(s_A + m * LD_A + half * 64);
#pragma unroll
        for (int i = 0; i < 16; i++) {
            float4 v = valid ? xr[i] : make_float4(0.f, 0.f, 0.f, 0.f);
            dst[i] = make_uint2(pack_bf2(v.x, v.y), pack_bf2(v.z, v.w));
        }
    } else if (tid < 192) {
        int m = tid - 128;
        int e = base + m;
        bool valid = e < EDGE_CNT;
        const float4* er = (const float4*)(ef + (long long)e * 16);
        uint2* dst = (uint2*)(s_A + m * LD_A + 128);
#pragma unroll
        for (int i = 0; i < 4; i++) {
            float4 v = valid ? er[i] : make_float4(0.f, 0.f, 0.f, 0.f);
            dst[i] = make_uint2(pack_bf2(v.x, v.y), pack_bf2(v.z, v.w));
        }
    }
    __syncthreads();

    // ---- GEMM1: h1 = relu(A[64x144] @ W1 + b1) ----
    {
        float c[8][4] = {};
#pragma unroll
        for (int k = 0; k < 9; k++) {
            uint32_t a[4];
            lda_frag(a, s_A + rows16 * LD_A + k * 16, LD_A, lane);
#pragma unroll
            for (int j = 0; j < 8; j++) {
                uint2 b = g_P1[(k * 16 + colh * 8 + j) * 32 + lane];
                mma_bf16(c[j], a, b.x, b.y);
            }
        }
#pragma unroll
        for (int j = 0; j < 8; j++) {
            int col = colh * 64 + j * 8 + tc * 2;
            float bb0 = s_b[col], bb1 = s_b[col + 1];
            *(uint32_t*)(s_H + (rows16 + g) * LD_H + col) =
                pack_bf2(fmaxf(c[j][0] + bb0, 0.f), fmaxf(c[j][1] + bb1, 0.f));
            *(uint32_t*)(s_H + (rows16 + 8 + g) * LD_H + col) =
                pack_bf2(fmaxf(c[j][2] + bb0, 0.f), fmaxf(c[j][3] + bb1, 0.f));
        }
    }
    __syncthreads();

    // ---- GEMM2: h2 = relu(h1[64x128] @ W2 + b2) -> s_A ----
    {
        float c[8][4] = {};
#pragma unroll
        for (int k = 0; k < 8; k++) {
            uint32_t a[4];
            lda_frag(a, s_H + rows16 * LD_H + k * 16, LD_H, lane);
#pragma unroll
            for (int j = 0; j < 8; j++) {
                uint2 b = g_P2[(k * 16 + colh * 8 + j) * 32 + lane];
                mma_bf16(c[j], a, b.x, b.y);
            }
        }
#pragma unroll
        for (int j = 0; j < 8; j++) {
            int col = colh * 64 + j * 8 + tc * 2;
            float bb0 = s_b[128 + col], bb1 = s_b[128 + col + 1];
            *(uint32_t*)(s_A + (rows16 + g) * LD_A + col) =
                pack_bf2(fmaxf(c[j][0] + bb0, 0.f), fmaxf(c[j][1] + bb1, 0.f));
            *(uint32_t*)(s_A + (rows16 + 8 + g) * LD_A + col) =
                pack_bf2(fmaxf(c[j][2] + bb0, 0.f), fmaxf(c[j][3] + bb1, 0.f));
        }
    }
    __syncthreads();

    // ---- GEMM3: msg = h2[64x128] @ W3 + b3; register scatter ----
    {
        float c[4][4] = {};
#pragma unroll
        for (int k = 0; k < 8; k++) {
            uint32_t a[4];
            lda_frag(a, s_A + rows16 * LD_A + k * 16, LD_A, lane);
#pragma unroll
            for (int j = 0; j < 4; j++) {
                uint2 b = g_P3[(k * 8 + colh * 4 + j) * 32 + lane];
                mma_bf16(c[j], a, b.x, b.y);
            }
        }
        int r0 = rows16 + g, r1 = rows16 + 8 + g;
        bool v0 = (base + r0) < EDGE_CNT, v1 = (base + r1) < EDGE_CNT;
        int t0 = v0 ? s_tgt[r0] : 0, t1 = v1 ? s_tgt[r1] : 0;
#pragma unroll
        for (int j = 0; j < 4; j++) {
            int cj = colh * 32 + j * 8 + tc * 2;
            float bb0 = s_b[256 + cj], bb1 = s_b[256 + cj + 1];
            if (v0) {
                asm volatile("red.global.add.v2.f32 [%0], {%1, %2};"
                             :: "l"(out + (long long)t0 * 64 + cj),
                                "f"(c[j][0] + bb0), "f"(c[j][1] + bb1) : "memory");
            }
            if (v1) {
                asm volatile("red.global.add.v2.f32 [%0], {%1, %2};"
                             :: "l"(out + (long long)t1 * 64 + cj),
                                "f"(c[j][2] + bb0), "f"(c[j][3] + bb1) : "memory");
            }
        }
        if (colh == 0 && tc == 0) {
            if (v0) atomicAdd(&g_counts[t0], 1.0f);
            if (v1) atomicAdd(&g_counts[t1], 1.0f);
        }
    }
}

extern "C" void kernel_launch(void* const* d_in, const int* in_sizes, int n_in,
                              void* d_out, int out_size) {
    const float *x = 0, *ef = 0, *W1 = 0, *W2 = 0, *W3 = 0, *b3 = 0;
    const float *b1 = 0, *b2 = 0;
    const void  *ei = 0;
    for (int i = 0; i < n_in; i++) {
        int s = in_sizes[i];
        if      (s == N_NODES * 64)  x  = (const float*)d_in[i];
        else if (s == 2 * EDGE_CNT)  ei = d_in[i];
        else if (s == EDGE_CNT * 16) ef = (const float*)d_in[i];
        else if (s == 144 * 128)     W1 = (const float*)d_in[i];
        else if (s == 128 * 128)     W2 = (const float*)d_in[i];
        else if (s == 128 * 64)      W3 = (const float*)d_in[i];
        else if (s == 64)            b3 = (const float*)d_in[i];
        else if (s == 128)           { if (!b1) b1 = (const float*)d_in[i]; else b2 = (const float*)d_in[i]; }
    }
    float* out = (float*)d_out;

    zero_kernel<<<2048, 256>>>(out);
    detect_kernel<<<16, 256>>>((const int*)ei);
    wpack_kernel<<<(10752 + 255) / 256, 256>>>(W1, W2, W3);
    gnn_mma<<<NUM_TILES, 256>>>(ei, ef, x, b1, b2, b3, out);
    finalize_kernel<<<(N_NODES * 64 + 255) / 256, 256>>>(x, out);
}

// round 13
// speedup vs baseline: 6.2530x; 1.2715x over previous
#include <cuda_runtime.h>
#include <cuda_bf16.h>
#include <stdint.h>

#define N_NODES  50000
#define EDGE_CNT 1250000
#define PAIR_M   128
#define NUM_PAIRS ((EDGE_CNT + PAIR_M - 1) / PAIR_M)

#define LD_A 168   // bf16 elems; 336B row stride (conflict-free ldmatrix)

// fragment-packed weights: slot (kstep, ntile, lane) -> uint2 {b0, b1}
__device__ __align__(16) uint2 g_P1[9 * 16 * 32];
__device__ __align__(16) uint2 g_P2[8 * 16 * 32];
__device__ __align__(16) uint2 g_P3[8 *  8 * 32];
__device__ __align__(16) __nv_bfloat16 g_xbf[N_NODES * 64];   // 6.4 MB
__device__ float g_counts[N_NODES];
__device__ int   g_idx_nonzero;

__device__ __forceinline__ uint32_t pack_bf2(float lo, float hi) {
    uint32_t r;
    asm("cvt.rn.bf16x2.f32 %0, %1, %2;" : "=r"(r) : "f"(hi), "f"(lo));
    return r;
}
__device__ __forceinline__ int load_edge(const void* eidx, int which, int e, bool is64) {
    long long v;
    if (is64) v = ((const long long*)eidx)[(long long)which * EDGE_CNT + e];
    else      v = ((const int*)eidx)[(long long)which * EDGE_CNT + e];
    int n = (int)v;
    return min(max(n, 0), N_NODES - 1);
}
__device__ __forceinline__ void lda_frag(uint32_t* a, const __nv_bfloat16* base, int lane) {
    int mat = lane >> 3, r = lane & 7;
    const __nv_bfloat16* p = base + ((mat & 1) * 8 + r) * LD_A + (mat >> 1) * 8;
    uint32_t addr = (uint32_t)__cvta_generic_to_shared(p);
    asm volatile("ldmatrix.sync.aligned.m8n8.x4.shared.b16 {%0,%1,%2,%3}, [%4];"
                 : "=r"(a[0]), "=r"(a[1]), "=r"(a[2]), "=r"(a[3]) : "r"(addr));
}
__device__ __forceinline__ void mma_bf16(float* c, const uint32_t* a, uint32_t b0, uint32_t b1) {
    asm volatile("mma.sync.aligned.m16n8k16.row.col.f32.bf16.bf16.f32 "
                 "{%0,%1,%2,%3}, {%4,%5,%6,%7}, {%8,%9}, {%0,%1,%2,%3};"
                 : "+f"(c[0]), "+f"(c[1]), "+f"(c[2]), "+f"(c[3])
                 : "r"(a[0]), "r"(a[1]), "r"(a[2]), "r"(a[3]), "r"(b0), "r"(b1));
}

__global__ void zero_kernel(float* __restrict__ out) {
    int i = blockIdx.x * blockDim.x + threadIdx.x;
    int stride = gridDim.x * blockDim.x;
    if (i == 0) g_idx_nonzero = 0;
    for (int j = i; j < N_NODES * 64; j += stride) out[j] = 0.0f;
    for (int j = i; j < N_NODES; j += stride) g_counts[j] = 0.0f;
}
__global__ void detect_kernel(const int* __restrict__ eidx32) {
    int i = blockIdx.x * blockDim.x + threadIdx.x;
    if (eidx32[2 * i + 1] != 0) atomicOr(&g_idx_nonzero, 1);
}
__global__ void xconv_kernel(const float* __restrict__ x) {
    int i = blockIdx.x * blockDim.x + threadIdx.x;
    if (i < N_NODES * 32) {
        float2 v = ((const float2*)x)[i];
        *(uint32_t*)(g_xbf + 2 * i) = pack_bf2(v.x, v.y);
    }
}
__global__ void wpack_kernel(const float* __restrict__ W1, const float* __restrict__ W2,
                             const float* __restrict__ W3) {
    int s = blockIdx.x * blockDim.x + threadIdx.x;
    if (s < 4608) {                               // GEMM1: 9 ksteps x 16 ntiles
        int K = s / 512, rem = s % 512, J = rem >> 5, lane = rem & 31;
        int g = lane >> 2, tc = lane & 3;
        int n = J * 8 + g, k0 = K * 16 + tc * 2;
        g_P1[s] = make_uint2(
            pack_bf2(W1[k0 * 128 + n],       W1[(k0 + 1) * 128 + n]),
            pack_bf2(W1[(k0 + 8) * 128 + n], W1[(k0 + 9) * 128 + n]));
    } else if (s < 4608 + 4096) {                 // GEMM2: 8 x 16
        int j = s - 4608;
        int K = j / 512, rem = j % 512, J = rem >> 5, lane = rem & 31;
        int g = lane >> 2, tc = lane & 3;
        int n = J * 8 + g, k0 = K * 16 + tc * 2;
        g_P2[j] = make_uint2(
            pack_bf2(W2[k0 * 128 + n],       W2[(k0 + 1) * 128 + n]),
            pack_bf2(W2[(k0 + 8) * 128 + n], W2[(k0 + 9) * 128 + n]));
    } else if (s < 4608 + 4096 + 2048) {          // GEMM3: 8 x 8
        int j = s - 8704;
        int K = j / 256, rem = j % 256, J = rem >> 5, lane = rem & 31;
        int g = lane >> 2, tc = lane & 3;
        int n = J * 8 + g, k0 = K * 16 + tc * 2;
        g_P3[j] = make_uint2(
            pack_bf2(W3[k0 * 64 + n],       W3[(k0 + 1) * 64 + n]),
            pack_bf2(W3[(k0 + 8) * 64 + n], W3[(k0 + 9) * 64 + n]));
    }
}
__global__ void finalize_kernel(const float* __restrict__ x, float* __restrict__ out) {
    int i = blockIdx.x * blockDim.x + threadIdx.x;
    if (i < N_NODES * 64) {
        float c = g_counts[i >> 6];
        out[i] = x[i] + out[i] / fmaxf(c, 1.0f);
    }
}

__global__ void __launch_bounds__(256, 2)
gnn_mma(const void* __restrict__ eidx, const float* __restrict__ ef,
        const float* __restrict__ b1, const float* __restrict__ b2,
        const float* __restrict__ b3, float* __restrict__ out) {
    __shared__ __align__(16) __nv_bfloat16 s_A[2][64 * LD_A];  // A1 / h1 / h2 per tile
    __shared__ float s_b[320];
    __shared__ int   s_tgt[PAIR_M];

    const int tid = threadIdx.x;
    const int w = tid >> 5, lane = tid & 31;
    const int strip = w & 3, colh = w >> 2;
    const int rows16 = strip * 16;
    const int g = lane >> 2, tc = lane & 3;
    const bool is64 = (g_idx_nonzero == 0);
    const int base = blockIdx.x * PAIR_M;

    // ---- bias ----
    if (tid < 128) { s_b[tid] = b1[tid]; s_b[128 + tid] = b2[tid]; }
    if (tid < 64)  s_b[256 + tid] = b3[tid];

    // ---- gather: 256 threads, each one (edge, half) -> bf16 row 128B ----
    {
        int m = tid >> 1, half = tid & 1;
        int e = base + m;
        bool valid = e < EDGE_CNT;
        int node = valid ? load_edge(eidx, half, e, is64) : 0;
        if (half) s_tgt[m] = node;
        const uint4* xr = (const uint4*)(g_xbf + (long long)node * 64);
        uint4* dst = (uint4*)(s_A[m >> 6] + (m & 63) * LD_A + half * 64);
        uint4 zero4 = make_uint4(0, 0, 0, 0);
#pragma unroll
        for (int i = 0; i < 8; i++) dst[i] = valid ? xr[i] : zero4;
    }
    // ef: threads 0..127, one edge each (16 fp32 -> 16 bf16 at cols 128..143)
    if (tid < 128) {
        int e = base + tid;
        bool valid = e < EDGE_CNT;
        const float4* er = (const float4*)(ef + (long long)e * 16);
        uint2* dst = (uint2*)(s_A[tid >> 6] + (tid & 63) * LD_A + 128);
#pragma unroll
        for (int i = 0; i < 4; i++) {
            float4 v = valid ? er[i] : make_float4(0.f, 0.f, 0.f, 0.f);
            dst[i] = make_uint2(pack_bf2(v.x, v.y), pack_bf2(v.z, v.w));
        }
    }
    __syncthreads();

    // ---- GEMM1: h1 = relu(A @ W1 + b1), both tiles share each B load ----
    {
        float c0[8][4] = {}, c1[8][4] = {};
#pragma unroll
        for (int k = 0; k < 9; k++) {
            uint32_t a0[4], a1[4];
            lda_frag(a0, s_A[0] + rows16 * LD_A + k * 16, lane);
            lda_frag(a1, s_A[1] + rows16 * LD_A + k * 16, lane);
#pragma unroll
            for (int j = 0; j < 8; j++) {
                uint2 b = g_P1[(k * 16 + colh * 8 + j) * 32 + lane];
                mma_bf16(c0[j], a0, b.x, b.y);
                mma_bf16(c1[j], a1, b.x, b.y);
            }
        }
        __syncthreads();   // all A1 reads done; buffers now reusable for h1
#pragma unroll
        for (int j = 0; j < 8; j++) {
            int col = colh * 64 + j * 8 + tc * 2;
            float bb0 = s_b[col], bb1 = s_b[col + 1];
            *(uint32_t*)(s_A[0] + (rows16 + g) * LD_A + col) =
                pack_bf2(fmaxf(c0[j][0] + bb0, 0.f), fmaxf(c0[j][1] + bb1, 0.f));
            *(uint32_t*)(s_A[0] + (rows16 + 8 + g) * LD_A + col) =
                pack_bf2(fmaxf(c0[j][2] + bb0, 0.f), fmaxf(c0[j][3] + bb1, 0.f));
            *(uint32_t*)(s_A[1] + (rows16 + g) * LD_A + col) =
                pack_bf2(fmaxf(c1[j][0] + bb0, 0.f), fmaxf(c1[j][1] + bb1, 0.f));
            *(uint32_t*)(s_A[1] + (rows16 + 8 + g) * LD_A + col) =
                pack_bf2(fmaxf(c1[j][2] + bb0, 0.f), fmaxf(c1[j][3] + bb1, 0.f));
        }
    }
    __syncthreads();

    // ---- GEMM2: h2 = relu(h1 @ W2 + b2), in-place ----
    {
        float c0[8][4] = {}, c1[8][4] = {};
#pragma unroll
        for (int k = 0; k < 8; k++) {
            uint32_t a0[4], a1[4];
            lda_frag(a0, s_A[0] + rows16 * LD_A + k * 16, lane);
            lda_frag(a1, s_A[1] + rows16 * LD_A + k * 16, lane);
#pragma unroll
            for (int j = 0; j < 8; j++) {
                uint2 b = g_P2[(k * 16 + colh * 8 + j) * 32 + lane];
                mma_bf16(c0[j], a0, b.x, b.y);
                mma_bf16(c1[j], a1, b.x, b.y);
            }
        }
        __syncthreads();
#pragma unroll
        for (int j = 0; j < 8; j++) {
            int col = colh * 64 + j * 8 + tc * 2;
            float bb0 = s_b[128 + col], bb1 = s_b[128 + col + 1];
            *(uint32_t*)(s_A[0] + (rows16 + g) * LD_A + col) =
                pack_bf2(fmaxf(c0[j][0] + bb0, 0.f), fmaxf(c0[j][1] + bb1, 0.f));
            *(uint32_t*)(s_A[0] + (rows16 + 8 + g) * LD_A + col) =
                pack_bf2(fmaxf(c0[j][2] + bb0, 0.f), fmaxf(c0[j][3] + bb1, 0.f));
            *(uint32_t*)(s_A[1] + (rows16 + g) * LD_A + col) =
                pack_bf2(fmaxf(c1[j][0] + bb0, 0.f), fmaxf(c1[j][1] + bb1, 0.f));
            *(uint32_t*)(s_A[1] + (rows16 + 8 + g) * LD_A + col) =
                pack_bf2(fmaxf(c1[j][2] + bb0, 0.f), fmaxf(c1[j][3] + bb1, 0.f));
        }
    }
    __syncthreads();

    // ---- GEMM3: msg = h2 @ W3 + b3; register scatter for both tiles ----
    {
        float c0[4][4] = {}, c1[4][4] = {};
#pragma unroll
        for (int k = 0; k < 8; k++) {
            uint32_t a0[4], a1[4];
            lda_frag(a0, s_A[0] + rows16 * LD_A + k * 16, lane);
            lda_frag(a1, s_A[1] + rows16 * LD_A + k * 16, lane);
#pragma unroll
            for (int j = 0; j < 4; j++) {
                uint2 b = g_P3[(k * 8 + colh * 4 + j) * 32 + lane];
                mma_bf16(c0[j], a0, b.x, b.y);
                mma_bf16(c1[j], a1, b.x, b.y);
            }
        }
#pragma unroll
        for (int t = 0; t < 2; t++) {
            float (*c)[4] = t ? c1 : c0;
            int m0 = t * 64 + rows16 + g, m1 = m0 + 8;
            bool v0 = (base + m0) < EDGE_CNT, v1 = (base + m1) < EDGE_CNT;
            int t0 = v0 ? s_tgt[m0] : 0, t1 = v1 ? s_tgt[m1] : 0;
#pragma unroll
            for (int j = 0; j < 4; j++) {
                int cj = colh * 32 + j * 8 + tc * 2;
                float bb0 = s_b[256 + cj], bb1 = s_b[256 + cj + 1];
                if (v0) {
                    asm volatile("red.global.add.v2.f32 [%0], {%1, %2};"
                                 :: "l"(out + (long long)t0 * 64 + cj),
                                    "f"(c[j][0] + bb0), "f"(c[j][1] + bb1) : "memory");
                }
                if (v1) {
                    asm volatile("red.global.add.v2.f32 [%0], {%1, %2};"
                                 :: "l"(out + (long long)t1 * 64 + cj),
                                    "f"(c[j][2] + bb0), "f"(c[j][3] + bb1) : "memory");
                }
            }
            if (colh == 0 && tc == 0) {
                if (v0) atomicAdd(&g_counts[t0], 1.0f);
                if (v1) atomicAdd(&g_counts[t1], 1.0f);
            }
        }
    }
}

extern "C" void kernel_launch(void* const* d_in, const int* in_sizes, int n_in,
                              void* d_out, int out_size) {
    const float *x = 0, *ef = 0, *W1 = 0, *W2 = 0, *W3 = 0, *b3 = 0;
    const float *b1 = 0, *b2 = 0;
    const void  *ei = 0;
    for (int i = 0; i < n_in; i++) {
        int s = in_sizes[i];
        if      (s == N_NODES * 64)  x  = (const float*)d_in[i];
        else if (s == 2 * EDGE_CNT)  ei = d_in[i];
        else if (s == EDGE_CNT * 16) ef = (const float*)d_in[i];
        else if (s == 144 * 128)     W1 = (const float*)d_in[i];
        else if (s == 128 * 128)     W2 = (const float*)d_in[i];
        else if (s == 128 * 64)      W3 = (const float*)d_in[i];
        else if (s == 64)            b3 = (const float*)d_in[i];
        else if (s == 128)           { if (!b1) b1 = (const float*)d_in[i]; else b2 = (const float*)d_in[i]; }
    }
    float* out = (float*)d_out;

    zero_kernel<<<2048, 256>>>(out);
    detect_kernel<<<16, 256>>>((const int*)ei);
    xconv_kernel<<<(N_NODES * 32 + 255) / 256, 256>>>(x);
    wpack_kernel<<<(10752 + 255) / 256, 256>>>(W1, W2, W3);
    gnn_mma<<<NUM_PAIRS, 256>>>(ei, ef, b1, b2, b3, out);
    finalize_kernel<<<(N_NODES * 64 + 255) / 256, 256>>>(x, out);
}

// round 15
// speedup vs baseline: 6.4114x; 1.0253x over previous
#include <cuda_runtime.h>
#include <cuda_bf16.h>
#include <stdint.h>

#define N_NODES  50000
#define EDGE_CNT 1250000
#define PAIR_M   128
#define NUM_PAIRS ((EDGE_CNT + PAIR_M - 1) / PAIR_M)

#define LD_A 168   // bf16 elems; 336B row stride (conflict-free ldmatrix)
#define LD_M 68    // msg fp32 stride: 272B, 16B-aligned rows, 4-bank skew

// fragment-packed weights: slot (kstep, ntile, lane) -> uint2 {b0, b1}
__device__ __align__(16) uint2 g_P1[9 * 16 * 32];
__device__ __align__(16) uint2 g_P2[8 * 16 * 32];
__device__ __align__(16) uint2 g_P3[8 *  8 * 32];
__device__ __align__(16) __nv_bfloat16 g_xbf[N_NODES * 64];
__device__ float g_counts[N_NODES];
__device__ int   g_idx_nonzero;

__device__ __forceinline__ uint32_t pack_bf2(float lo, float hi) {
    uint32_t r;
    asm("cvt.rn.bf16x2.f32 %0, %1, %2;" : "=r"(r) : "f"(hi), "f"(lo));
    return r;
}
__device__ __forceinline__ int load_edge(const void* eidx, int which, int e, bool is64) {
    long long v;
    if (is64) v = ((const long long*)eidx)[(long long)which * EDGE_CNT + e];
    else      v = ((const int*)eidx)[(long long)which * EDGE_CNT + e];
    int n = (int)v;
    return min(max(n, 0), N_NODES - 1);
}
__device__ __forceinline__ void lda_frag(uint32_t* a, const __nv_bfloat16* base, int lane) {
    int mat = lane >> 3, r = lane & 7;
    const __nv_bfloat16* p = base + ((mat & 1) * 8 + r) * LD_A + (mat >> 1) * 8;
    uint32_t addr = (uint32_t)__cvta_generic_to_shared(p);
    asm volatile("ldmatrix.sync.aligned.m8n8.x4.shared.b16 {%0,%1,%2,%3}, [%4];"
                 : "=r"(a[0]), "=r"(a[1]), "=r"(a[2]), "=r"(a[3]) : "r"(addr));
}
__device__ __forceinline__ void mma_bf16(float* c, const uint32_t* a, uint32_t b0, uint32_t b1) {
    asm volatile("mma.sync.aligned.m16n8k16.row.col.f32.bf16.bf16.f32 "
                 "{%0,%1,%2,%3}, {%4,%5,%6,%7}, {%8,%9}, {%0,%1,%2,%3};"
                 : "+f"(c[0]), "+f"(c[1]), "+f"(c[2]), "+f"(c[3])
                 : "r"(a[0]), "r"(a[1]), "r"(a[2]), "r"(a[3]), "r"(b0), "r"(b1));
}

__global__ void zero_kernel(float* __restrict__ out) {
    int i = blockIdx.x * blockDim.x + threadIdx.x;
    int stride = gridDim.x * blockDim.x;
    if (i == 0) g_idx_nonzero = 0;
    for (int j = i; j < N_NODES * 64; j += stride) out[j] = 0.0f;
    for (int j = i; j < N_NODES; j += stride) g_counts[j] = 0.0f;
}
__global__ void detect_kernel(const int* __restrict__ eidx32) {
    int i = blockIdx.x * blockDim.x + threadIdx.x;
    if (eidx32[2 * i + 1] != 0) atomicOr(&g_idx_nonzero, 1);
}
__global__ void xconv_kernel(const float* __restrict__ x) {
    int i = blockIdx.x * blockDim.x + threadIdx.x;
    if (i < N_NODES * 32) {
        float2 v = ((const float2*)x)[i];
        *(uint32_t*)(g_xbf + 2 * i) = pack_bf2(v.x, v.y);
    }
}
__global__ void wpack_kernel(const float* __restrict__ W1, const float* __restrict__ W2,
                             const float* __restrict__ W3) {
    int s = blockIdx.x * blockDim.x + threadIdx.x;
    if (s < 4608) {
        int K = s / 512, rem = s % 512, J = rem >> 5, lane = rem & 31;
        int g = lane >> 2, tc = lane & 3;
        int n = J * 8 + g, k0 = K * 16 + tc * 2;
        g_P1[s] = make_uint2(
            pack_bf2(W1[k0 * 128 + n],       W1[(k0 + 1) * 128 + n]),
            pack_bf2(W1[(k0 + 8) * 128 + n], W1[(k0 + 9) * 128 + n]));
    } else if (s < 4608 + 4096) {
        int j = s - 4608;
        int K = j / 512, rem = j % 512, J = rem >> 5, lane = rem & 31;
        int g = lane >> 2, tc = lane & 3;
        int n = J * 8 + g, k0 = K * 16 + tc * 2;
        g_P2[j] = make_uint2(
            pack_bf2(W2[k0 * 128 + n],       W2[(k0 + 1) * 128 + n]),
            pack_bf2(W2[(k0 + 8) * 128 + n], W2[(k0 + 9) * 128 + n]));
    } else if (s < 4608 + 4096 + 2048) {
        int j = s - 8704;
        int K = j / 256, rem = j % 256, J = rem >> 5, lane = rem & 31;
        int g = lane >> 2, tc = lane & 3;
        int n = J * 8 + g, k0 = K * 16 + tc * 2;
        g_P3[j] = make_uint2(
            pack_bf2(W3[k0 * 64 + n],       W3[(k0 + 1) * 64 + n]),
            pack_bf2(W3[(k0 + 8) * 64 + n], W3[(k0 + 9) * 64 + n]));
    }
}
__global__ void finalize_kernel(const float* __restrict__ x, float* __restrict__ out) {
    int i = blockIdx.x * blockDim.x + threadIdx.x;
    if (i < N_NODES * 64) {
        float c = g_counts[i >> 6];
        out[i] = x[i] + out[i] / fmaxf(c, 1.0f);
    }
}

__global__ void __launch_bounds__(256, 2)
gnn_mma(const void* __restrict__ eidx, const float* __restrict__ ef,
        const float* __restrict__ b1, const float* __restrict__ b2,
        const float* __restrict__ b3, float* __restrict__ out) {
    __shared__ __align__(16) __nv_bfloat16 s_A[2][64 * LD_A];  // A1/h1/h2; GEMM3 msg overlay
    __shared__ float s_b[320];
    __shared__ int   s_tgt[PAIR_M];

    const int tid = threadIdx.x;
    const int w = tid >> 5, lane = tid & 31;
    const int strip = w & 3, colh = w >> 2;
    const int rows16 = strip * 16;
    const int g = lane >> 2, tc = lane & 3;
    const bool is64 = (g_idx_nonzero == 0);
    const int base = blockIdx.x * PAIR_M;
    float* s_msg = (float*)s_A;   // [128][LD_M] fp32 overlay (34816B <= 43008B)

    // ---- bias ----
    if (tid < 128) { s_b[tid] = b1[tid]; s_b[128 + tid] = b2[tid]; }
    if (tid < 64)  s_b[256 + tid] = b3[tid];

    // ---- gather ----
    {
        int m = tid >> 1, half = tid & 1;
        int e = base + m;
        bool valid = e < EDGE_CNT;
        int node = valid ? load_edge(eidx, half, e, is64) : 0;
        if (half) s_tgt[m] = node;
        const uint4* xr = (const uint4*)(g_xbf + (long long)node * 64);
        uint4* dst = (uint4*)(s_A[m >> 6] + (m & 63) * LD_A + half * 64);
        uint4 zero4 = make_uint4(0, 0, 0, 0);
#pragma unroll
        for (int i = 0; i < 8; i++) dst[i] = valid ? xr[i] : zero4;
    }
    if (tid < 128) {
        int e = base + tid;
        bool valid = e < EDGE_CNT;
        const float4* er = (const float4*)(ef + (long long)e * 16);
        uint2* dst = (uint2*)(s_A[tid >> 6] + (tid & 63) * LD_A + 128);
#pragma unroll
        for (int i = 0; i < 4; i++) {
            float4 v = valid ? er[i] : make_float4(0.f, 0.f, 0.f, 0.f);
            dst[i] = make_uint2(pack_bf2(v.x, v.y), pack_bf2(v.z, v.w));
        }
    }
    __syncthreads();

    // ---- GEMM1 ----
    {
        float c0[8][4] = {}, c1[8][4] = {};
#pragma unroll
        for (int k = 0; k < 9; k++) {
            uint32_t a0[4], a1[4];
            lda_frag(a0, s_A[0] + rows16 * LD_A + k * 16, lane);
            lda_frag(a1, s_A[1] + rows16 * LD_A + k * 16, lane);
#pragma unroll
            for (int j = 0; j < 8; j++) {
                uint2 b = g_P1[(k * 16 + colh * 8 + j) * 32 + lane];
                mma_bf16(c0[j], a0, b.x, b.y);
                mma_bf16(c1[j], a1, b.x, b.y);
            }
        }
        __syncthreads();
#pragma unroll
        for (int j = 0; j < 8; j++) {
            int col = colh * 64 + j * 8 + tc * 2;
            float bb0 = s_b[col], bb1 = s_b[col + 1];
            *(uint32_t*)(s_A[0] + (rows16 + g) * LD_A + col) =
                pack_bf2(fmaxf(c0[j][0] + bb0, 0.f), fmaxf(c0[j][1] + bb1, 0.f));
            *(uint32_t*)(s_A[0] + (rows16 + 8 + g) * LD_A + col) =
                pack_bf2(fmaxf(c0[j][2] + bb0, 0.f), fmaxf(c0[j][3] + bb1, 0.f));
            *(uint32_t*)(s_A[1] + (rows16 + g) * LD_A + col) =
                pack_bf2(fmaxf(c1[j][0] + bb0, 0.f), fmaxf(c1[j][1] + bb1, 0.f));
            *(uint32_t*)(s_A[1] + (rows16 + 8 + g) * LD_A + col) =
                pack_bf2(fmaxf(c1[j][2] + bb0, 0.f), fmaxf(c1[j][3] + bb1, 0.f));
        }
    }
    __syncthreads();

    // ---- GEMM2 (in-place) ----
    {
        float c0[8][4] = {}, c1[8][4] = {};
#pragma unroll
        for (int k = 0; k < 8; k++) {
            uint32_t a0[4], a1[4];
            lda_frag(a0, s_A[0] + rows16 * LD_A + k * 16, lane);
            lda_frag(a1, s_A[1] + rows16 * LD_A + k * 16, lane);
#pragma unroll
            for (int j = 0; j < 8; j++) {
                uint2 b = g_P2[(k * 16 + colh * 8 + j) * 32 + lane];
                mma_bf16(c0[j], a0, b.x, b.y);
                mma_bf16(c1[j], a1, b.x, b.y);
            }
        }
        __syncthreads();
#pragma unroll
        for (int j = 0; j < 8; j++) {
            int col = colh * 64 + j * 8 + tc * 2;
            float bb0 = s_b[128 + col], bb1 = s_b[128 + col + 1];
            *(uint32_t*)(s_A[0] + (rows16 + g) * LD_A + col) =
                pack_bf2(fmaxf(c0[j][0] + bb0, 0.f), fmaxf(c0[j][1] + bb1, 0.f));
            *(uint32_t*)(s_A[0] + (rows16 + 8 + g) * LD_A + col) =
                pack_bf2(fmaxf(c0[j][2] + bb0, 0.f), fmaxf(c0[j][3] + bb1, 0.f));
            *(uint32_t*)(s_A[1] + (rows16 + g) * LD_A + col) =
                pack_bf2(fmaxf(c1[j][0] + bb0, 0.f), fmaxf(c1[j][1] + bb1, 0.f));
            *(uint32_t*)(s_A[1] + (rows16 + 8 + g) * LD_A + col) =
                pack_bf2(fmaxf(c1[j][2] + bb0, 0.f), fmaxf(c1[j][3] + bb1, 0.f));
        }
    }
    __syncthreads();

    // ---- GEMM3: msg = h2 @ W3 + b3 -> smem; then coalesced red.v4 scatter ----
    {
        float c0[4][4] = {}, c1[4][4] = {};
#pragma unroll
        for (int k = 0; k < 8; k++) {
            uint32_t a0[4], a1[4];
            lda_frag(a0, s_A[0] + rows16 * LD_A + k * 16, lane);
            lda_frag(a1, s_A[1] + rows16 * LD_A + k * 16, lane);
#pragma unroll
            for (int j = 0; j < 4; j++) {
                uint2 b = g_P3[(k * 8 + colh * 4 + j) * 32 + lane];
                mma_bf16(c0[j], a0, b.x, b.y);
                mma_bf16(c1[j], a1, b.x, b.y);
            }
        }
        __syncthreads();   // h2 reads complete; s_A region becomes fp32 msg buffer
#pragma unroll
        for (int j = 0; j < 4; j++) {
            int cj = colh * 32 + j * 8 + tc * 2;
            float bb0 = s_b[256 + cj], bb1 = s_b[256 + cj + 1];
            *(float2*)(s_msg + (rows16 + g) * LD_M + cj) =
                make_float2(c0[j][0] + bb0, c0[j][1] + bb1);
            *(float2*)(s_msg + (rows16 + 8 + g) * LD_M + cj) =
                make_float2(c0[j][2] + bb0, c0[j][3] + bb1);
            *(float2*)(s_msg + (64 + rows16 + g) * LD_M + cj) =
                make_float2(c1[j][0] + bb0, c1[j][1] + bb1);
            *(float2*)(s_msg + (64 + rows16 + 8 + g) * LD_M + cj) =
                make_float2(c1[j][2] + bb0, c1[j][3] + bb1);
        }
        __syncthreads();

        // scatter: 2048 slots (128 edges x 16 col-quads), 8 per thread
        for (int s = 0; s < 8; s++) {
            int slot = tid + 256 * s;
            int m = slot >> 4;          // edge row 0..127
            int q = slot & 15;          // col quad 0..15
            if (base + m < EDGE_CNT) {
                int tgt = s_tgt[m];
                float4 v = *(float4*)(s_msg + m * LD_M + q * 4);
                asm volatile("red.global.add.v4.f32 [%0], {%1, %2, %3, %4};"
                             :: "l"(out + (long long)tgt * 64 + q * 4),
                                "f"(v.x), "f"(v.y), "f"(v.z), "f"(v.w) : "memory");
                if (q == 0) atomicAdd(&g_counts[tgt], 1.0f);
            }
        }
    }
}

extern "C" void kernel_launch(void* const* d_in, const int* in_sizes, int n_in,
                              void* d_out, int out_size) {
    const float *x = 0, *ef = 0, *W1 = 0, *W2 = 0, *W3 = 0, *b3 = 0;
    const float *b1 = 0, *b2 = 0;
    const void  *ei = 0;
    for (int i = 0; i < n_in; i++) {
        int s = in_sizes[i];
        if      (s == N_NODES * 64)  x  = (const float*)d_in[i];
        else if (s == 2 * EDGE_CNT)  ei = d_in[i];
        else if (s == EDGE_CNT * 16) ef = (const float*)d_in[i];
        else if (s == 144 * 128)     W1 = (const float*)d_in[i];
        else if (s == 128 * 128)     W2 = (const float*)d_in[i];
        else if (s == 128 * 64)      W3 = (const float*)d_in[i];
        else if (s == 64)            b3 = (const float*)d_in[i];
        else if (s == 128)           { if (!b1) b1 = (const float*)d_in[i]; else b2 = (const float*)d_in[i]; }
    }
    float* out = (float*)d_out;

    zero_kernel<<<2048, 256>>>(out);
    detect_kernel<<<16, 256>>>((const int*)ei);
    xconv_kernel<<<(N_NODES * 32 + 255) / 256, 256>>>(x);
    wpack_kernel<<<(10752 + 255) / 256, 256>>>(W1, W2, W3);
    gnn_mma<<<NUM_PAIRS, 256>>>(ei, ef, b1, b2, b3, out);
    finalize_kernel<<<(N_NODES * 64 + 255) / 256, 256>>>(x, out);
}